// round 1
// baseline (speedup 1.0000x reference)
#include <cuda_runtime.h>
#include <math.h>

#define NN 100000
#define NE 1600000
#define FD 128
#define NG 128
#define GF 32

// ---------------- scratch (device globals: no allocations allowed) ----------
__device__ __align__(16) float g_agg[(size_t)NN * FD];
__device__ __align__(16) float g_h0 [(size_t)NN * FD];
__device__ __align__(16) float g_h1 [(size_t)NN * FD];
__device__ int   g_deg[NN];
__device__ int   g_rowptr[NN + 1];
__device__ int   g_fill[NN];
__device__ int   g_col[NE];
__device__ float g_psum[NG * FD];
__device__ float g_pmax[NG * FD];
__device__ int   g_pcnt[NG];
__device__ int   g_bsum[128];

// ---------------- helpers ---------------------------------------------------
__device__ __forceinline__ void atomicMaxF(float* addr, float v) {
    if (v >= 0.f) atomicMax((int*)addr, __float_as_int(v));
    else          atomicMin((unsigned int*)addr, __float_as_uint(v));
}

// ---------------- CSR build -------------------------------------------------
__global__ void k_init() {
    int i = blockIdx.x * blockDim.x + threadIdx.x;
    if (i < NN) { g_deg[i] = 0; g_fill[i] = 0; }
    if (i < NG * FD) { g_psum[i] = 0.f; g_pmax[i] = -INFINITY; }
    if (i < NG) g_pcnt[i] = 0;
}

__global__ void k_hist(const int* __restrict__ edges) {
    int e = blockIdx.x * blockDim.x + threadIdx.x;
    if (e < NE) atomicAdd(&g_deg[edges[NE + e]], 1);
}

#define SCAN_B 1024
__global__ void k_scanA() {
    __shared__ int sm[SCAN_B];
    int i = blockIdx.x * SCAN_B + threadIdx.x;
    int v = (i < NN) ? g_deg[i] : 0;
    sm[threadIdx.x] = v;
    __syncthreads();
    for (int off = 1; off < SCAN_B; off <<= 1) {
        int t = (threadIdx.x >= off) ? sm[threadIdx.x - off] : 0;
        __syncthreads();
        sm[threadIdx.x] += t;
        __syncthreads();
    }
    if (i < NN) g_rowptr[i] = sm[threadIdx.x] - v;   // exclusive
    if (threadIdx.x == SCAN_B - 1) g_bsum[blockIdx.x] = sm[SCAN_B - 1];
}

__global__ void k_scanB(int nb) {
    if (threadIdx.x == 0) {
        int acc = 0;
        for (int b = 0; b < nb; b++) { int t = g_bsum[b]; g_bsum[b] = acc; acc += t; }
    }
}

__global__ void k_scanC() {
    int i = blockIdx.x * SCAN_B + threadIdx.x;
    if (i < NN) g_rowptr[i] += g_bsum[blockIdx.x];
    if (i == 0) g_rowptr[NN] = NE;
}

__global__ void k_fillcol(const int* __restrict__ edges) {
    int e = blockIdx.x * blockDim.x + threadIdx.x;
    if (e < NE) {
        int t = edges[NE + e];
        int p = g_rowptr[t] + atomicAdd(&g_fill[t], 1);
        g_col[p] = edges[e];
    }
}

// ---------------- neighbor mean aggregation (warp per node) -----------------
__global__ void k_aggregate(const float* __restrict__ X, float* __restrict__ AGG) {
    int node = blockIdx.x * 8 + (threadIdx.x >> 5);
    int lane = threadIdx.x & 31;
    if (node >= NN) return;
    int beg = g_rowptr[node], end = g_rowptr[node + 1];
    const float4* Xv = (const float4*)X;
    float4 s = make_float4(0.f, 0.f, 0.f, 0.f);
    int e = beg;
    for (; e + 1 < end; e += 2) {
        int s0 = g_col[e], s1 = g_col[e + 1];
        float4 v0 = Xv[(size_t)s0 * 32 + lane];
        float4 v1 = Xv[(size_t)s1 * 32 + lane];
        s.x += v0.x + v1.x; s.y += v0.y + v1.y;
        s.z += v0.z + v1.z; s.w += v0.w + v1.w;
    }
    if (e < end) {
        float4 v = Xv[(size_t)g_col[e] * 32 + lane];
        s.x += v.x; s.y += v.y; s.z += v.z; s.w += v.w;
    }
    float sc = 1.f / fmaxf((float)(end - beg), 1.f);
    ((float4*)AGG)[(size_t)node * 32 + lane] =
        make_float4(s.x * sc, s.y * sc, s.z * sc, s.w * sc);
}

// ---------------- fused SAGE transform: OUT = act(X@Wr + AGG@Wl + b) --------
// block tile 64 nodes x 128 outs; thread tile 4 nodes x 8 outs; 256 threads.
#define TRANS_SMEM (FD * FD * 4 + 64 * 132 * 4)
__global__ void k_transform(const float* __restrict__ X, const float* __restrict__ AGG,
                            const float* __restrict__ Wr, const float* __restrict__ Wl,
                            const float* __restrict__ bias, float* __restrict__ OUT,
                            int relu) {
    extern __shared__ float sm[];
    float* Wsm = sm;                 // 128*128
    float* Asm = sm + FD * FD;       // 64 rows x 132 (padded)
    const int tid = threadIdx.x;
    const int og  = tid & 15;        // output group: o = og*8 .. +7
    const int ng  = tid >> 4;        // node group:  n = ng*4 .. +3
    const int node0 = blockIdx.x * 64;

    float acc[4][8];
#pragma unroll
    for (int i = 0; i < 4; i++)
#pragma unroll
        for (int j = 0; j < 8; j++) acc[i][j] = 0.f;

    for (int c = 0; c < 2; c++) {
        const float* W = c ? Wl : Wr;
        const float* A = c ? AGG : X;
        __syncthreads();
        const float4* W4 = (const float4*)W;
        float4* Wsm4 = (float4*)Wsm;
#pragma unroll
        for (int r = 0; r < 16; r++) Wsm4[tid + r * 256] = W4[tid + r * 256];
#pragma unroll
        for (int r = 0; r < 8; r++) {
            int idx = tid + r * 256;         // float4 index in 64x32 tile
            int n = idx >> 5, kq = idx & 31;
            int gn = node0 + n;
            float4 v = make_float4(0.f, 0.f, 0.f, 0.f);
            if (gn < NN) v = ((const float4*)A)[(size_t)gn * 32 + kq];
            float* dst = &Asm[n * 132 + kq * 4];
            dst[0] = v.x; dst[1] = v.y; dst[2] = v.z; dst[3] = v.w;
        }
        __syncthreads();
        const float* arow = &Asm[(ng * 4) * 132];
#pragma unroll 2
        for (int k = 0; k < FD; k++) {
            const float4* wp = (const float4*)&Wsm[k * FD + og * 8];
            float4 w0 = wp[0], w1 = wp[1];
#pragma unroll
            for (int i = 0; i < 4; i++) {
                float a = arow[i * 132 + k];
                acc[i][0] += a * w0.x; acc[i][1] += a * w0.y;
                acc[i][2] += a * w0.z; acc[i][3] += a * w0.w;
                acc[i][4] += a * w1.x; acc[i][5] += a * w1.y;
                acc[i][6] += a * w1.z; acc[i][7] += a * w1.w;
            }
        }
    }

    float b[8];
#pragma unroll
    for (int j = 0; j < 8; j++) b[j] = bias[og * 8 + j];
#pragma unroll
    for (int i = 0; i < 4; i++) {
        int n = node0 + ng * 4 + i;
        if (n < NN) {
            float* o = OUT + (size_t)n * FD + og * 8;
#pragma unroll
            for (int j = 0; j < 8; j++) {
                float v = acc[i][j] + b[j];
                if (relu) v = fmaxf(v, 0.f);
                o[j] = v;
            }
        }
    }
}

// ---------------- pooling (sorted batch_idx, warp-local segments) -----------
__global__ void k_pool(const float* __restrict__ H, const int* __restrict__ batch) {
    int wg   = (blockIdx.x * blockDim.x + threadIdx.x) >> 5;
    int lane = threadIdx.x & 31;
    int n0 = wg * 64;
    if (n0 >= NN) return;
    int n1 = min(n0 + 64, NN);
    const float4* Hv = (const float4*)H;
    float4 s = make_float4(0.f, 0.f, 0.f, 0.f);
    float4 m = make_float4(-INFINITY, -INFINITY, -INFINITY, -INFINITY);
    int cnt = 0, cur = batch[n0];
    for (int n = n0; n < n1; n++) {
        int g = batch[n];
        if (g != cur) {
            int base = cur * FD + lane * 4;
            atomicAdd(&g_psum[base + 0], s.x); atomicAdd(&g_psum[base + 1], s.y);
            atomicAdd(&g_psum[base + 2], s.z); atomicAdd(&g_psum[base + 3], s.w);
            atomicMaxF(&g_pmax[base + 0], m.x); atomicMaxF(&g_pmax[base + 1], m.y);
            atomicMaxF(&g_pmax[base + 2], m.z); atomicMaxF(&g_pmax[base + 3], m.w);
            if (lane == 0) atomicAdd(&g_pcnt[cur], cnt);
            s = make_float4(0.f, 0.f, 0.f, 0.f);
            m = make_float4(-INFINITY, -INFINITY, -INFINITY, -INFINITY);
            cnt = 0; cur = g;
        }
        float4 v = Hv[(size_t)n * 32 + lane];
        s.x += v.x; s.y += v.y; s.z += v.z; s.w += v.w;
        m.x = fmaxf(m.x, v.x); m.y = fmaxf(m.y, v.y);
        m.z = fmaxf(m.z, v.z); m.w = fmaxf(m.w, v.w);
        cnt++;
    }
    int base = cur * FD + lane * 4;
    atomicAdd(&g_psum[base + 0], s.x); atomicAdd(&g_psum[base + 1], s.y);
    atomicAdd(&g_psum[base + 2], s.z); atomicAdd(&g_psum[base + 3], s.w);
    atomicMaxF(&g_pmax[base + 0], m.x); atomicMaxF(&g_pmax[base + 1], m.y);
    atomicMaxF(&g_pmax[base + 2], m.z); atomicMaxF(&g_pmax[base + 3], m.w);
    if (lane == 0) atomicAdd(&g_pcnt[cur], cnt);
}

// ---------------- readout head ---------------------------------------------
__global__ void k_readout(const float* __restrict__ gfeat,
                          const float* __restrict__ Wg, const float* __restrict__ bg,
                          const float* __restrict__ Wo, const float* __restrict__ bo,
                          float* __restrict__ out) {
    __shared__ float flat[3 * FD];
    __shared__ float logits[2];
    int g = blockIdx.x, o = threadIdx.x;     // 128 threads
    float cnt = fmaxf((float)g_pcnt[g], 1.f);
    flat[o]       = g_psum[g * FD + o] / cnt;
    flat[FD + o]  = g_pmax[g * FD + o];
    float acc = bg[o];
#pragma unroll
    for (int k = 0; k < GF; k++) acc += gfeat[g * GF + k] * Wg[k * FD + o];
    flat[2 * FD + o] = acc;
    __syncthreads();
    if (o < 2) {
        float l = bo[o];
        for (int j = 0; j < 3 * FD; j++) l += flat[j] * Wo[j * 2 + o];
        logits[o] = l;
    }
    __syncthreads();
    if (o < 2) {
        float mm  = fmaxf(logits[0], logits[1]);
        float lse = mm + logf(expf(logits[0] - mm) + expf(logits[1] - mm));
        out[g * 2 + o] = logits[o] - lse;
    }
}

// ---------------- launch -----------------------------------------------------
extern "C" void kernel_launch(void* const* d_in, const int* in_sizes, int n_in,
                              void* d_out, int out_size) {
    const float* x     = (const float*)d_in[0];
    const int*   edges = (const int*)  d_in[1];
    const int*   batch = (const int*)  d_in[2];
    const float* gfeat = (const float*)d_in[3];
    const float* Wl0   = (const float*)d_in[4];
    const float* bl0   = (const float*)d_in[5];
    const float* Wr0   = (const float*)d_in[6];
    const float* Wl1   = (const float*)d_in[7];
    const float* bl1   = (const float*)d_in[8];
    const float* Wr1   = (const float*)d_in[9];
    const float* Wg    = (const float*)d_in[10];
    const float* bg    = (const float*)d_in[11];
    const float* Wo    = (const float*)d_in[12];
    const float* bo    = (const float*)d_in[13];
    float* out = (float*)d_out;

    cudaFuncSetAttribute(k_transform, cudaFuncAttributeMaxDynamicSharedMemorySize,
                         TRANS_SMEM);

    float *p_agg, *p_h0, *p_h1;
    cudaGetSymbolAddress((void**)&p_agg, g_agg);
    cudaGetSymbolAddress((void**)&p_h0,  g_h0);
    cudaGetSymbolAddress((void**)&p_h1,  g_h1);

    const int scan_nb = (NN + SCAN_B - 1) / SCAN_B;   // 98

    k_init<<<(NN + 255) / 256, 256>>>();
    k_hist<<<(NE + 255) / 256, 256>>>(edges);
    k_scanA<<<scan_nb, SCAN_B>>>();
    k_scanB<<<1, 32>>>(scan_nb);
    k_scanC<<<scan_nb, SCAN_B>>>();
    k_fillcol<<<(NE + 255) / 256, 256>>>(edges);

    // layer 0
    k_aggregate<<<(NN + 7) / 8, 256>>>(x, p_agg);
    k_transform<<<(NN + 63) / 64, 256, TRANS_SMEM>>>(x, p_agg, Wr0, Wl0, bl0, p_h0, 1);
    // layer 1
    k_aggregate<<<(NN + 7) / 8, 256>>>(p_h0, p_agg);
    k_transform<<<(NN + 63) / 64, 256, TRANS_SMEM>>>(p_h0, p_agg, Wr1, Wl1, bl1, p_h1, 0);

    // pooling + head
    int pool_warps  = (NN + 63) / 64;
    int pool_blocks = (pool_warps * 32 + 255) / 256;
    k_pool<<<pool_blocks, 256>>>(p_h1, batch);
    k_readout<<<NG, FD>>>(gfeat, Wg, bg, Wo, bo, out);
}

// round 4
// speedup vs baseline: 1.6208x; 1.6208x over previous
#include <cuda_runtime.h>
#include <cuda_bf16.h>
#include <cstdint>
#include <math.h>

#define NN 100000
#define NE 1600000
#define FD 128
#define NG 128
#define GF 32

// ---------------- scratch (device globals; no allocations allowed) ----------
__device__ __align__(16) __nv_bfloat16 g_Uh[(size_t)NN * 256];  // [X | AGG] hi
__device__ __align__(16) __nv_bfloat16 g_Ul[(size_t)NN * 256];  // [X | AGG] lo
__device__ __align__(16) __nv_bfloat16 g_Bh[2 * 128 * 256];     // W^T hi, per layer
__device__ __align__(16) __nv_bfloat16 g_Bl[2 * 128 * 256];     // W^T lo
__device__ __align__(16) float g_h0[(size_t)NN * FD];
__device__ __align__(16) float g_h1[(size_t)NN * FD];
__device__ int   g_deg[NN];
__device__ int   g_rowptr[NN + 1];
__device__ int   g_fill[NN];
__device__ int   g_col[NE];
__device__ float g_psum[NG * FD];
__device__ float g_pmax[NG * FD];
__device__ int   g_pcnt[NG];
__device__ int   g_bsum[128];

// ---------------- small helpers ---------------------------------------------
__device__ __forceinline__ void atomicMaxF(float* addr, float v) {
    if (v >= 0.f) atomicMax((int*)addr, __float_as_int(v));
    else          atomicMin((unsigned int*)addr, __float_as_uint(v));
}

__device__ __forceinline__ void bsplit(float v, unsigned short& hi, unsigned short& lo) {
    __nv_bfloat16 h = __float2bfloat16(v);
    float r = v - __bfloat162float(h);
    __nv_bfloat16 l = __float2bfloat16(r);
    hi = __bfloat16_as_ushort(h);
    lo = __bfloat16_as_ushort(l);
}

__device__ __forceinline__ uint32_t smem_u32(const void* p) {
    uint32_t a;
    asm("{ .reg .u64 t; cvta.to.shared.u64 t, %1; cvt.u32.u64 %0, t; }"
        : "=r"(a) : "l"(p));
    return a;
}

__device__ __forceinline__ void ldsm4(uint32_t* r, uint32_t addr) {
    asm volatile("ldmatrix.sync.aligned.m8n8.x4.shared.b16 {%0,%1,%2,%3}, [%4];"
                 : "=r"(r[0]), "=r"(r[1]), "=r"(r[2]), "=r"(r[3]) : "r"(addr));
}
__device__ __forceinline__ void ldsm2(uint32_t* r, uint32_t addr) {
    asm volatile("ldmatrix.sync.aligned.m8n8.x2.shared.b16 {%0,%1}, [%2];"
                 : "=r"(r[0]), "=r"(r[1]) : "r"(addr));
}
__device__ __forceinline__ void mma_bf16(float* c, const uint32_t* a, const uint32_t* b) {
    asm volatile(
        "mma.sync.aligned.m16n8k16.row.col.f32.bf16.bf16.f32 "
        "{%0,%1,%2,%3}, {%4,%5,%6,%7}, {%8,%9}, {%0,%1,%2,%3};"
        : "+f"(c[0]), "+f"(c[1]), "+f"(c[2]), "+f"(c[3])
        : "r"(a[0]), "r"(a[1]), "r"(a[2]), "r"(a[3]), "r"(b[0]), "r"(b[1]));
}

// ---------------- CSR build -------------------------------------------------
__global__ void k_init() {
    int i = blockIdx.x * blockDim.x + threadIdx.x;
    if (i < NN) { g_deg[i] = 0; g_fill[i] = 0; }
    if (i < NG * FD) { g_psum[i] = 0.f; g_pmax[i] = -INFINITY; }
    if (i < NG) g_pcnt[i] = 0;
}

__global__ void k_hist(const int* __restrict__ edges) {
    int e = blockIdx.x * blockDim.x + threadIdx.x;
    if (e < NE) atomicAdd(&g_deg[edges[NE + e]], 1);
}

#define SCAN_B 1024
__global__ void k_scanA() {
    __shared__ int sm[SCAN_B];
    int i = blockIdx.x * SCAN_B + threadIdx.x;
    int v = (i < NN) ? g_deg[i] : 0;
    sm[threadIdx.x] = v;
    __syncthreads();
    for (int off = 1; off < SCAN_B; off <<= 1) {
        int t = (threadIdx.x >= off) ? sm[threadIdx.x - off] : 0;
        __syncthreads();
        sm[threadIdx.x] += t;
        __syncthreads();
    }
    if (i < NN) g_rowptr[i] = sm[threadIdx.x] - v;   // exclusive
    if (threadIdx.x == SCAN_B - 1) g_bsum[blockIdx.x] = sm[SCAN_B - 1];
}

__global__ void k_scanB(int nb) {
    if (threadIdx.x == 0) {
        int acc = 0;
        for (int b = 0; b < nb; b++) { int t = g_bsum[b]; g_bsum[b] = acc; acc += t; }
    }
}

__global__ void k_scanC() {
    int i = blockIdx.x * SCAN_B + threadIdx.x;
    if (i < NN) g_rowptr[i] += g_bsum[blockIdx.x];
    if (i == 0) g_rowptr[NN] = NE;
}

__global__ void k_fillcol(const int* __restrict__ edges) {
    int e = blockIdx.x * blockDim.x + threadIdx.x;
    if (e < NE) {
        int t = edges[NE + e];
        int p = g_rowptr[t] + atomicAdd(&g_fill[t], 1);
        g_col[p] = edges[e];
    }
}

// ---------------- weight prep: V = [Wr;Wl] -> Bt[n][k] hi/lo bf16 -----------
__global__ void k_prepw(const float* __restrict__ Wr0, const float* __restrict__ Wl0,
                        const float* __restrict__ Wr1, const float* __restrict__ Wl1) {
    int idx = blockIdx.x * 256 + threadIdx.x;        // 65536 total
    int L = idx >> 15;
    int rem = idx & 32767;
    int k = rem >> 7, n = rem & 127;
    const float* Wr = L ? Wr1 : Wr0;
    const float* Wl = L ? Wl1 : Wl0;
    float v = (k < FD) ? Wr[k * FD + n] : Wl[(k - FD) * FD + n];
    unsigned short hi, lo;
    bsplit(v, hi, lo);
    g_Bh[L * 32768 + n * 256 + k] = __ushort_as_bfloat16(hi);
    g_Bl[L * 32768 + n * 256 + k] = __ushort_as_bfloat16(lo);
}

// ---------------- split X into bf16 hi/lo (cols 0..127 of U) ----------------
__global__ void k_split_x(const float* __restrict__ X) {
    int i = blockIdx.x * 256 + threadIdx.x;          // over NN*32 float4
    if (i >= NN * 32) return;
    float4 v = ((const float4*)X)[i];
    int node = i >> 5, q = (i & 31) * 4;
    union { unsigned short s[4]; uint2 u; } ph, pl;
    bsplit(v.x, ph.s[0], pl.s[0]);
    bsplit(v.y, ph.s[1], pl.s[1]);
    bsplit(v.z, ph.s[2], pl.s[2]);
    bsplit(v.w, ph.s[3], pl.s[3]);
    *(uint2*)(g_Uh + (size_t)node * 256 + q) = ph.u;
    *(uint2*)(g_Ul + (size_t)node * 256 + q) = pl.u;
}

// ---------------- neighbor mean aggregation -> bf16 hi/lo (cols 128..255) ---
__global__ void k_aggregate(const float* __restrict__ X) {
    int node = blockIdx.x * 8 + (threadIdx.x >> 5);
    int lane = threadIdx.x & 31;
    if (node >= NN) return;
    int beg = g_rowptr[node], end = g_rowptr[node + 1];
    const float4* Xv = (const float4*)X;
    float4 s = make_float4(0.f, 0.f, 0.f, 0.f);
    int e = beg;
    for (; e + 3 < end; e += 4) {
        int i0 = g_col[e], i1 = g_col[e + 1], i2 = g_col[e + 2], i3 = g_col[e + 3];
        float4 a = Xv[(size_t)i0 * 32 + lane];
        float4 b = Xv[(size_t)i1 * 32 + lane];
        float4 c = Xv[(size_t)i2 * 32 + lane];
        float4 d = Xv[(size_t)i3 * 32 + lane];
        s.x += (a.x + b.x) + (c.x + d.x);
        s.y += (a.y + b.y) + (c.y + d.y);
        s.z += (a.z + b.z) + (c.z + d.z);
        s.w += (a.w + b.w) + (c.w + d.w);
    }
    for (; e < end; e++) {
        float4 v = Xv[(size_t)g_col[e] * 32 + lane];
        s.x += v.x; s.y += v.y; s.z += v.z; s.w += v.w;
    }
    float sc = 1.f / fmaxf((float)(end - beg), 1.f);
    union { unsigned short s[4]; uint2 u; } ph, pl;
    bsplit(s.x * sc, ph.s[0], pl.s[0]);
    bsplit(s.y * sc, ph.s[1], pl.s[1]);
    bsplit(s.z * sc, ph.s[2], pl.s[2]);
    bsplit(s.w * sc, ph.s[3], pl.s[3]);
    size_t off = (size_t)node * 256 + 128 + lane * 4;
    *(uint2*)(g_Uh + off) = ph.u;
    *(uint2*)(g_Ul + off) = pl.u;
}

// ---------------- mma.sync GEMM: OUT = act(U @ V + b), bf16x3 compensation --
// CTA: 128 nodes x 128 outs; 8 warps as 2(M)x4(N); warp tile 64x32.
// K = 256, chunked by 64; smem tiles padded to pitch 72 bf16 (conflict-free).
#define TP 72
#define TILE_B (128 * TP * 2)                 // 18432 bytes per tile
#define GEMM_SMEM (4 * TILE_B + 512)

__device__ __forceinline__ void load_chunk(__nv_bfloat16* dst,
                                           const __nv_bfloat16* __restrict__ src,
                                           int row0, int rowmax, int kofs) {
    for (int i = threadIdx.x; i < 1024; i += 256) {  // uint4 units (8 bf16)
        int r = i >> 3, q = i & 7;
        int gr = row0 + r;
        uint4 v = make_uint4(0, 0, 0, 0);
        if (gr < rowmax) v = *(const uint4*)(src + (size_t)gr * 256 + kofs + q * 8);
        *(uint4*)(dst + r * TP + q * 8) = v;
    }
}

__global__ __launch_bounds__(256, 2) void k_gemm(
    const __nv_bfloat16* __restrict__ Uh, const __nv_bfloat16* __restrict__ Ul,
    const __nv_bfloat16* __restrict__ Bh, const __nv_bfloat16* __restrict__ Bl,
    const float* __restrict__ bias, float* __restrict__ OUT,
    __nv_bfloat16* __restrict__ NUh, __nv_bfloat16* __restrict__ NUl,
    int relu, int wsplit)
{
    extern __shared__ char smem[];
    __nv_bfloat16* sUh = (__nv_bfloat16*)smem;
    __nv_bfloat16* sUl = (__nv_bfloat16*)(smem + TILE_B);
    __nv_bfloat16* sBh = (__nv_bfloat16*)(smem + 2 * TILE_B);
    __nv_bfloat16* sBl = (__nv_bfloat16*)(smem + 3 * TILE_B);
    float* sbias = (float*)(smem + 4 * TILE_B);

    const int tid = threadIdx.x, wid = tid >> 5, lid = tid & 31;
    const int wm = wid >> 2, wn = wid & 3;
    const int node0 = blockIdx.x * 128;

    if (tid < FD) sbias[tid] = bias[tid];

    float acc[4][4][4];
#pragma unroll
    for (int mt = 0; mt < 4; mt++)
#pragma unroll
        for (int nt = 0; nt < 4; nt++)
#pragma unroll
            for (int j = 0; j < 4; j++) acc[mt][nt][j] = 0.f;

    uint32_t aUh = smem_u32(sUh), aUl = smem_u32(sUl);
    uint32_t aBh = smem_u32(sBh), aBl = smem_u32(sBl);
    // ldmatrix lane addressing
    const uint32_t a_lane = (uint32_t)((lid & 15) * (TP * 2) + ((lid >> 4) << 4));
    const uint32_t b_lane = (uint32_t)((lid & 7) * (TP * 2) + (((lid >> 3) & 1) << 4));

    for (int c = 0; c < 4; c++) {
        load_chunk(sUh, Uh, node0, NN, c * 64);
        load_chunk(sUl, Ul, node0, NN, c * 64);
        load_chunk(sBh, Bh, 0, 128, c * 64);
        load_chunk(sBl, Bl, 0, 128, c * 64);
        __syncthreads();
#pragma unroll
        for (int ks = 0; ks < 4; ks++) {
            uint32_t ah[4][4], al[4][4];
#pragma unroll
            for (int mt = 0; mt < 4; mt++) {
                uint32_t roff = (uint32_t)((wm * 64 + mt * 16) * (TP * 2) + ks * 32);
                ldsm4(ah[mt], aUh + roff + a_lane);
                ldsm4(al[mt], aUl + roff + a_lane);
            }
#pragma unroll
            for (int nt = 0; nt < 4; nt++) {
                uint32_t bh[2], bl[2];
                uint32_t roff = (uint32_t)((wn * 32 + nt * 8) * (TP * 2) + ks * 32);
                ldsm2(bh, aBh + roff + b_lane);
                ldsm2(bl, aBl + roff + b_lane);
#pragma unroll
                for (int mt = 0; mt < 4; mt++) {
                    mma_bf16(acc[mt][nt], ah[mt], bh);
                    mma_bf16(acc[mt][nt], al[mt], bh);
                    mma_bf16(acc[mt][nt], ah[mt], bl);
                }
            }
        }
        __syncthreads();
    }

    // epilogue: c-fragment: (row = t/4 [+8], col = 2*(t%4) [+1])
    const int tq = lid >> 2, tr = lid & 3;
#pragma unroll
    for (int mt = 0; mt < 4; mt++) {
#pragma unroll
        for (int h = 0; h < 2; h++) {
            int node = node0 + wm * 64 + mt * 16 + tq + h * 8;
            if (node >= NN) continue;
#pragma unroll
            for (int nt = 0; nt < 4; nt++) {
                int col = wn * 32 + nt * 8 + tr * 2;
                float v0 = acc[mt][nt][h * 2 + 0] + sbias[col];
                float v1 = acc[mt][nt][h * 2 + 1] + sbias[col + 1];
                if (relu) { v0 = fmaxf(v0, 0.f); v1 = fmaxf(v1, 0.f); }
                *(float2*)(OUT + (size_t)node * FD + col) = make_float2(v0, v1);
                if (wsplit) {
                    union { unsigned short s[2]; uint32_t u; } ph, pl;
                    bsplit(v0, ph.s[0], pl.s[0]);
                    bsplit(v1, ph.s[1], pl.s[1]);
                    *(uint32_t*)(NUh + (size_t)node * 256 + col) = ph.u;
                    *(uint32_t*)(NUl + (size_t)node * 256 + col) = pl.u;
                }
            }
        }
    }
}

// ---------------- pooling (sorted batch_idx, warp-local segments) -----------
__global__ void k_pool(const float* __restrict__ H, const int* __restrict__ batch) {
    int wg   = (blockIdx.x * blockDim.x + threadIdx.x) >> 5;
    int lane = threadIdx.x & 31;
    int n0 = wg * 64;
    if (n0 >= NN) return;
    int n1 = min(n0 + 64, NN);
    const float4* Hv = (const float4*)H;
    float4 s = make_float4(0.f, 0.f, 0.f, 0.f);
    float4 m = make_float4(-INFINITY, -INFINITY, -INFINITY, -INFINITY);
    int cnt = 0, cur = batch[n0];
    for (int n = n0; n < n1; n++) {
        int g = batch[n];
        if (g != cur) {
            int base = cur * FD + lane * 4;
            atomicAdd(&g_psum[base + 0], s.x); atomicAdd(&g_psum[base + 1], s.y);
            atomicAdd(&g_psum[base + 2], s.z); atomicAdd(&g_psum[base + 3], s.w);
            atomicMaxF(&g_pmax[base + 0], m.x); atomicMaxF(&g_pmax[base + 1], m.y);
            atomicMaxF(&g_pmax[base + 2], m.z); atomicMaxF(&g_pmax[base + 3], m.w);
            if (lane == 0) atomicAdd(&g_pcnt[cur], cnt);
            s = make_float4(0.f, 0.f, 0.f, 0.f);
            m = make_float4(-INFINITY, -INFINITY, -INFINITY, -INFINITY);
            cnt = 0; cur = g;
        }
        float4 v = Hv[(size_t)n * 32 + lane];
        s.x += v.x; s.y += v.y; s.z += v.z; s.w += v.w;
        m.x = fmaxf(m.x, v.x); m.y = fmaxf(m.y, v.y);
        m.z = fmaxf(m.z, v.z); m.w = fmaxf(m.w, v.w);
        cnt++;
    }
    int base = cur * FD + lane * 4;
    atomicAdd(&g_psum[base + 0], s.x); atomicAdd(&g_psum[base + 1], s.y);
    atomicAdd(&g_psum[base + 2], s.z); atomicAdd(&g_psum[base + 3], s.w);
    atomicMaxF(&g_pmax[base + 0], m.x); atomicMaxF(&g_pmax[base + 1], m.y);
    atomicMaxF(&g_pmax[base + 2], m.z); atomicMaxF(&g_pmax[base + 3], m.w);
    if (lane == 0) atomicAdd(&g_pcnt[cur], cnt);
}

// ---------------- readout head ---------------------------------------------
__global__ void k_readout(const float* __restrict__ gfeat,
                          const float* __restrict__ Wg, const float* __restrict__ bg,
                          const float* __restrict__ Wo, const float* __restrict__ bo,
                          float* __restrict__ out) {
    __shared__ float flat[3 * FD];
    __shared__ float logits[2];
    int g = blockIdx.x, o = threadIdx.x;     // 128 threads
    float cnt = fmaxf((float)g_pcnt[g], 1.f);
    flat[o]       = g_psum[g * FD + o] / cnt;
    flat[FD + o]  = g_pmax[g * FD + o];
    float acc = bg[o];
#pragma unroll
    for (int k = 0; k < GF; k++) acc += gfeat[g * GF + k] * Wg[k * FD + o];
    flat[2 * FD + o] = acc;
    __syncthreads();
    if (o < 2) {
        float l = bo[o];
        for (int j = 0; j < 3 * FD; j++) l += flat[j] * Wo[j * 2 + o];
        logits[o] = l;
    }
    __syncthreads();
    if (o < 2) {
        float mm  = fmaxf(logits[0], logits[1]);
        float lse = mm + logf(expf(logits[0] - mm) + expf(logits[1] - mm));
        out[g * 2 + o] = logits[o] - lse;
    }
}

// ---------------- launch -----------------------------------------------------
extern "C" void kernel_launch(void* const* d_in, const int* in_sizes, int n_in,
                              void* d_out, int out_size) {
    const float* x     = (const float*)d_in[0];
    const int*   edges = (const int*)  d_in[1];
    const int*   batch = (const int*)  d_in[2];
    const float* gfeat = (const float*)d_in[3];
    const float* Wl0   = (const float*)d_in[4];
    const float* bl0   = (const float*)d_in[5];
    const float* Wr0   = (const float*)d_in[6];
    const float* Wl1   = (const float*)d_in[7];
    const float* bl1   = (const float*)d_in[8];
    const float* Wr1   = (const float*)d_in[9];
    const float* Wg    = (const float*)d_in[10];
    const float* bg    = (const float*)d_in[11];
    const float* Wo    = (const float*)d_in[12];
    const float* bo    = (const float*)d_in[13];
    float* out = (float*)d_out;

    cudaFuncSetAttribute(k_gemm, cudaFuncAttributeMaxDynamicSharedMemorySize,
                         GEMM_SMEM);

    __nv_bfloat16 *pUh, *pUl, *pBh, *pBl;
    float *p_h0, *p_h1;
    cudaGetSymbolAddress((void**)&pUh, g_Uh);
    cudaGetSymbolAddress((void**)&pUl, g_Ul);
    cudaGetSymbolAddress((void**)&pBh, g_Bh);
    cudaGetSymbolAddress((void**)&pBl, g_Bl);
    cudaGetSymbolAddress((void**)&p_h0, g_h0);
    cudaGetSymbolAddress((void**)&p_h1, g_h1);

    const int scan_nb = (NN + SCAN_B - 1) / SCAN_B;   // 98
    const int gemm_nb = (NN + 127) / 128;             // 782

    k_init<<<(NN + 255) / 256, 256>>>();
    k_hist<<<(NE + 255) / 256, 256>>>(edges);
    k_scanA<<<scan_nb, SCAN_B>>>();
    k_scanB<<<1, 32>>>(scan_nb);
    k_scanC<<<scan_nb, SCAN_B>>>();
    k_fillcol<<<(NE + 255) / 256, 256>>>(edges);

    k_prepw<<<256, 256>>>(Wr0, Wl0, Wr1, Wl1);
    k_split_x<<<(NN * 32 + 255) / 256, 256>>>(x);

    // layer 0
    k_aggregate<<<(NN + 7) / 8, 256>>>(x);
    k_gemm<<<gemm_nb, 256, GEMM_SMEM>>>(pUh, pUl, pBh, pBl, bl0, p_h0,
                                        pUh, pUl, 1, 1);
    // layer 1
    k_aggregate<<<(NN + 7) / 8, 256>>>(p_h0);
    k_gemm<<<gemm_nb, 256, GEMM_SMEM>>>(pUh, pUl, pBh + 32768, pBl + 32768, bl1,
                                        p_h1, nullptr, nullptr, 0, 0);

    // pooling + head
    int pool_warps  = (NN + 63) / 64;
    int pool_blocks = (pool_warps * 32 + 255) / 256;
    k_pool<<<pool_blocks, 256>>>(p_h1, batch);
    k_readout<<<NG, FD>>>(gfeat, Wg, bg, Wo, bo, out);
}